// round 3
// baseline (speedup 1.0000x reference)
#include <cuda_runtime.h>

// FilteredNoise: per-frame zero-phase FIR synthesis from real spectrum + OLA.
// out[b, f*64 + t] += GAIN * conv(2*noise[b,f]-1, hann .* linphase(irfft(filter[b,f])))[t]
//
// Direct-form implementation:
//   ir[n]  = (1/129)(X[0] + 2 sum_{k=1..64} X[k] cos(2pi k n / 129)),  ir symmetric
//   h[64-n] = ir[n]*win[64-n], h[64+n] = ir[n]*win[64+n]   (win = periodic Hann 129)
//   frame[t] = sum_s n2[s] h[t-s]   (t in [0,192))
// Each CTA owns 2048 output samples (32 hop blocks) of one batch row and the
// 34 frames (32 + 2 history) contributing to them -> every output sample is
// written exactly once with a plain store. GAIN and the 1/129 + factor-2
// scaling are folded into X at load time.

#define THREADS 256

__global__ __launch_bounds__(THREADS)
void filtered_noise_kernel(const float* __restrict__ filt,
                           const float* __restrict__ noise,
                           float* __restrict__ out,
                           int F, long outlen)
{
    // smem layouts (strides chosen coprime with 32 banks):
    //  sXT[k][lf]   : 65 x 40 (frames padded 34->40 for float4 tiles), scaled X, transposed
    //  sH [lf][m]   : 34 x 145, padded IR rows: 8 zeros | h[0..128] | 8 zeros
    //  sN [lf][s]   : 34 x 65 (stride 65), n2 = 2*noise-1
    //  sc [r]       : cos(2*pi*r/129), r = 0..128
    __shared__ __align__(16) float sXT[65 * 40];
    __shared__ float sH[34 * 145];
    __shared__ float sN[34 * 65];
    __shared__ float sc[129];

    const int tid = threadIdx.x;
    const int g   = blockIdx.x;   // group of 32 hop blocks
    const int b   = blockIdx.y;
    const long base_f = (long)g * 32 - 2;   // global frame index of local frame 0

    const float* fb = filt  + (long)b * F * 65;
    const float* nb = noise + (long)b * F * 64;

    // ---- tables + tile loads ----
    if (tid < 129) sc[tid] = cospif((float)(2 * tid) / 129.0f);

    for (int i = tid; i < 34 * 145; i += THREADS) sH[i] = 0.0f;

    for (int i = tid; i < 34 * 65; i += THREADS) {
        int lf = i / 65;
        int k  = i - lf * 65;
        long f = base_f + lf;
        float v = 0.0f;
        if (f >= 0 && f < F) v = fb[f * 65 + k];
        // fold irfft normalization (1/129), the factor-2 for k>0, and GAIN=0.01
        float s = (k == 0) ? (0.01f / 129.0f) : (0.02f / 129.0f);
        sXT[k * 40 + lf] = v * s;
    }
    for (int i = tid; i < 65 * 6; i += THREADS) {        // zero pad frames 34..39
        int k = i / 6, j = i - k * 6;
        sXT[k * 40 + 34 + j] = 0.0f;
    }
    for (int i = tid; i < 34 * 64; i += THREADS) {
        int lf = i >> 6, s = i & 63;
        long f = base_f + lf;
        float v = 0.5f;                                   // -> n2 = 0 when invalid
        if (f >= 0 && f < F) v = nb[f * 64 + s];
        sN[lf * 65 + s] = 2.0f * v - 1.0f;
    }
    __syncthreads();

    // ---- Phase A: ir[n] for n=0..64, 8 frames per thread, then scatter h ----
    const float4* sXT4 = (const float4*)sXT;             // 10 float4 per k-row
    for (int u = tid; u < 5 * 65; u += THREADS) {
        int ft = u / 65;                                  // frame tile (8 frames)
        int n  = u - ft * 65;                             // IR index 0..64
        float acc[8];
        #pragma unroll
        for (int i = 0; i < 8; ++i) acc[i] = 0.0f;

        int r = 0;                                        // (k*n) mod 129
        #pragma unroll
        for (int k = 0; k < 65; ++k) {
            float c  = sc[r];
            float4 xa = sXT4[k * 10 + ft * 2];
            float4 xb = sXT4[k * 10 + ft * 2 + 1];
            acc[0] = fmaf(xa.x, c, acc[0]);
            acc[1] = fmaf(xa.y, c, acc[1]);
            acc[2] = fmaf(xa.z, c, acc[2]);
            acc[3] = fmaf(xa.w, c, acc[3]);
            acc[4] = fmaf(xb.x, c, acc[4]);
            acc[5] = fmaf(xb.y, c, acc[5]);
            acc[6] = fmaf(xb.z, c, acc[6]);
            acc[7] = fmaf(xb.w, c, acc[7]);
            r += n;
            if (r >= 129) r -= 129;
        }
        // h[64-n] = ir[n]*win[64-n];  h[64+n] = ir[n]*win[64+n]  (n=0 writes twice, same value)
        float w1 = 0.5f - 0.5f * sc[64 - n];
        float w2 = 0.5f - 0.5f * sc[64 + n];
        #pragma unroll
        for (int j = 0; j < 8; ++j) {
            int lf = ft * 8 + j;
            if (lf < 34) {
                sH[lf * 145 + 8 + 64 - n] = acc[j] * w1;
                sH[lf * 145 + 8 + 64 + n] = acc[j] * w2;
            }
        }
    }
    __syncthreads();

    // ---- Phase B: FIR conv + OLA. warp -> tau (uniform), lane -> hop block ----
    const int w    = tid >> 5;
    const int lane = tid & 31;
    const int tau  = w << 3;        // 0,8,...,56 (uniform per warp)
    const int hb   = lane;          // local hop block 0..31

    float acc[8];
    #pragma unroll
    for (int i = 0; i < 8; ++i) acc[i] = 0.0f;

    #pragma unroll
    for (int d = 0; d < 3; ++d) {   // frame offset: f = hopblock - d
        long fglob = (long)g * 32 + hb - d;
        if (fglob >= 0 && fglob < F) {
            const int lf = hb - d + 2;            // local frame row, always in [0,33]
            const int t0 = tau + (d << 6);        // frame-local output base, mult of 8
            int s_lo, steps;                      // trimmed, always multiple of 8
            if (d == 0)      { s_lo = 0;   steps = tau + 8; }
            else if (d == 1) { s_lo = 0;   steps = 64;      }
            else             { s_lo = tau; steps = 64 - tau; }

            const float* hrow = sH + lf * 145 + 8;   // hrow[-8..136] valid (pads = 0)
            const float* nrow = sN + lf * 65;

            // sliding window: wcur[i] = h[t0 + i - sb]
            float wcur[8];
            #pragma unroll
            for (int i = 0; i < 8; ++i) wcur[i] = hrow[t0 + i - s_lo];

            const int s_end = s_lo + steps;
            for (int sb = s_lo; sb < s_end; sb += 8) {
                const int bidx = t0 - sb;
                float wnew[8];                      // wnew[q] = h[bidx - 1 - q]
                #pragma unroll
                for (int j = 0; j < 8; ++j) wnew[j] = hrow[bidx - 1 - j];
                #pragma unroll
                for (int j = 0; j < 8; ++j) {       // step s = sb + j
                    float nv = nrow[sb + j];
                    #pragma unroll
                    for (int i = 0; i < 8; ++i) {
                        // h[t0+i-s]: i>=j from wcur, else from wnew
                        float hv = (i >= j) ? wcur[i - j] : wnew[j - 1 - i];
                        acc[i] = fmaf(nv, hv, acc[i]);
                    }
                }
                #pragma unroll
                for (int i = 0; i < 8; ++i) wcur[i] = wnew[7 - i];
            }
        }
    }

    // each (g, hb, tau) tile of 8 samples is owned by exactly one thread
    long p0 = (long)g * 2048 + (long)hb * 64 + tau;
    if (p0 < outlen) {  // outlen and p0 are multiples of 8 -> full tile in-bounds
        float* op = out + (long)b * outlen + p0;
        reinterpret_cast<float4*>(op)[0] = make_float4(acc[0], acc[1], acc[2], acc[3]);
        reinterpret_cast<float4*>(op)[1] = make_float4(acc[4], acc[5], acc[6], acc[7]);
    }
}

extern "C" void kernel_launch(void* const* d_in, const int* in_sizes, int n_in,
                              void* d_out, int out_size)
{
    const float* d_filter = (const float*)d_in[0];   // [B, F, 65]
    const float* d_noise  = (const float*)d_in[1];   // [B, F, 64]
    float* d_o = (float*)d_out;                      // [B, (F-1)*64 + 192]

    const long nframes = (long)in_sizes[0] / 65;     // B*F
    const long B = ((long)out_size - 64 * nframes) / 128;
    const int  F = (int)(nframes / B);
    const long outlen = (long)(F - 1) * 64 + 192;
    const int  G = (int)((outlen + 2047) / 2048);

    dim3 grid((unsigned)G, (unsigned)B);
    filtered_noise_kernel<<<grid, THREADS>>>(d_filter, d_noise, d_o, F, outlen);
}

// round 4
// speedup vs baseline: 1.0381x; 1.0381x over previous
#include <cuda_runtime.h>

// FilteredNoise: per-frame zero-phase FIR synthesis from real spectrum + OLA.
//   ir[n]  = (1/129)(X[0] + 2 sum_{k=1..64} X[k] cos(2pi k n / 129)),  ir symmetric
//   h[64-n] = ir[n]*win[64-n], h[64+n] = ir[n]*win[64+n]   (win = periodic Hann 129)
//   out[b, f*64 + t] += GAIN * sum_s n2[s] h[t-s]
//
// Each CTA owns 2048 output samples (32 hop blocks) of one batch row and the
// 34 frames (32 + 2 history) contributing to them -> every output sample is
// written exactly once. GAIN and irfft scaling are folded into X at load.
//
// Phase A: Chebyshev recurrence for cos(2pi k n/129) (no table gathers, no mod),
//          8 frames x 4 n register tile, packed fma.rn.f32x2 over frame pairs.
// Phase B: FIR conv with fma.rn.f32x2 over step pairs:
//          acc2_i += (n[s], n[s+1]) .* (h[t-s], h[t-s-1]); horizontal add at end.

#define THREADS 256
typedef unsigned long long u64;

__device__ __forceinline__ u64 pk2(float lo, float hi) {
    u64 r; asm("mov.b64 %0, {%1, %2};" : "=l"(r) : "f"(lo), "f"(hi)); return r;
}
__device__ __forceinline__ void upk2(u64 v, float& lo, float& hi) {
    asm("mov.b64 {%0, %1}, %2;" : "=f"(lo), "=f"(hi) : "l"(v));
}
__device__ __forceinline__ void ffma2(u64& d, u64 a, u64 b) {
    asm("fma.rn.f32x2 %0, %1, %2, %0;" : "+l"(d) : "l"(a), "l"(b));
}

__global__ __launch_bounds__(THREADS)
void filtered_noise_kernel(const float* __restrict__ filt,
                           const float* __restrict__ noise,
                           float* __restrict__ out,
                           int F, long outlen)
{
    // sXT[k][lf]: 65 x 36 (frames padded 34->36, even stride for u64 pairs)
    // sH [lf][m]: 34 x 145, rows: 8 zeros | h[0..128] | 8 zeros
    // sN [lf][s]: 34 x 65 (odd stride: conflict-free across lanes)
    __shared__ __align__(16) float sXT[65 * 36];
    __shared__ float sH[34 * 145];
    __shared__ float sN[34 * 65];

    const int tid = threadIdx.x;
    const int g   = blockIdx.x;             // group of 32 hop blocks
    const int b   = blockIdx.y;
    const long base_f = (long)g * 32 - 2;   // global frame of local frame 0

    const float* fb = filt  + (long)b * F * 65;
    const float* nb = noise + (long)b * F * 64;

    // ---- fills ----
    // sXT: lf fast -> conflict-free STS (LDG is strided; L2/DRAM have headroom)
    for (int i = tid; i < 65 * 36; i += THREADS) {
        int k = i / 36, lf = i - k * 36;
        long f = base_f + lf;
        float v = 0.0f;
        if (lf < 34 && f >= 0 && f < F) v = fb[f * 65 + k];
        float s = (k == 0) ? (0.01f / 129.0f) : (0.02f / 129.0f);
        sXT[i] = v * s;
    }
    // zero only the sH pads (phase A writes h[0..128] fully for all 34 rows)
    for (int i = tid; i < 34 * 16; i += THREADS) {
        int lf = i >> 4, j = i & 15;
        sH[lf * 145 + (j < 8 ? j : 129 + j)] = 0.0f;
    }
    for (int i = tid; i < 34 * 64; i += THREADS) {
        int lf = i >> 6, s = i & 63;
        long f = base_f + lf;
        float v = 0.5f;                     // -> n2 = 0 when frame invalid
        if (f >= 0 && f < F) v = nb[f * 64 + s];
        sN[lf * 65 + s] = 2.0f * v - 1.0f;
    }
    __syncthreads();

    // ---- Phase A: ir[n] via Chebyshev recurrence, 8 frames x 4 n / thread ----
    if (tid < 85) {
        const int ft = tid % 5;             // frames 8ft..8ft+7 (pairs 4ft..4ft+3)
        const int nt = tid / 5;             // n = 4nt..4nt+3 (n>64 discarded)

        float c[4], cp[4], coef[4];
        #pragma unroll
        for (int i = 0; i < 4; ++i) {
            float c1 = cospif((float)(2 * (4 * nt + i)) / 129.0f);
            coef[i] = 2.0f * c1;
            c[i]  = 1.0f;    // cos(0 * theta)
            cp[i] = c1;      // cos(-theta)
        }

        u64 acc[4][4];
        #pragma unroll
        for (int p = 0; p < 4; ++p)
            #pragma unroll
            for (int i = 0; i < 4; ++i) acc[p][i] = 0ull;

        const u64* xrow = (const u64*)(sXT + 8 * ft);   // 18 u64 per k-row
        #pragma unroll 5
        for (int k = 0; k < 65; ++k) {
            u64 x0 = xrow[k * 18 + 0];
            u64 x1 = xrow[k * 18 + 1];
            u64 x2 = xrow[k * 18 + 2];
            u64 x3 = xrow[k * 18 + 3];
            #pragma unroll
            for (int i = 0; i < 4; ++i) {
                u64 cc = pk2(c[i], c[i]);
                ffma2(acc[0][i], x0, cc);
                ffma2(acc[1][i], x1, cc);
                ffma2(acc[2][i], x2, cc);
                ffma2(acc[3][i], x3, cc);
                float cn = fmaf(coef[i], c[i], -cp[i]);   // cos((k+1)theta)
                cp[i] = c[i]; c[i] = cn;
            }
        }

        #pragma unroll
        for (int i = 0; i < 4; ++i) {
            int n = 4 * nt + i;
            if (n <= 64) {
                float w1 = 0.5f - 0.5f * cospif((float)(2 * (64 - n)) / 129.0f);
                float w2 = 0.5f - 0.5f * cospif((float)(2 * (64 + n)) / 129.0f);
                #pragma unroll
                for (int p = 0; p < 4; ++p) {
                    float ir0, ir1; upk2(acc[p][i], ir0, ir1);
                    int lf = 8 * ft + 2 * p;
                    if (lf < 34) {
                        float* r0 = sH + lf * 145 + 8;
                        r0[64 - n] = ir0 * w1;
                        r0[64 + n] = ir0 * w2;
                    }
                    if (lf + 1 < 34) {
                        float* r1 = sH + (lf + 1) * 145 + 8;
                        r1[64 - n] = ir1 * w1;
                        r1[64 + n] = ir1 * w2;
                    }
                }
            }
        }
    }
    __syncthreads();

    // ---- Phase B: FIR conv + OLA. warp -> tau (uniform), lane -> hop block ----
    const int w    = tid >> 5;
    const int lane = tid & 31;
    const int tau  = w << 3;        // 0,8,...,56
    const int hb   = lane;          // local hop block 0..31

    u64 acc2[8];                    // acc2[i] halves: (even-s part, odd-s part)
    #pragma unroll
    for (int i = 0; i < 8; ++i) acc2[i] = 0ull;

    #pragma unroll
    for (int d = 0; d < 3; ++d) {   // frame offset: f = hopblock - d
        long fglob = (long)g * 32 + hb - d;
        if (fglob >= 0 && fglob < F) {
            const int lf = hb - d + 2;            // local frame row, in [0,33]
            const int t0 = tau + (d << 6);        // frame-local output base (mult of 8)
            int s_lo, s_end;                      // multiples of 8
            if (d == 0)      { s_lo = 0;   s_end = tau + 8; }
            else if (d == 1) { s_lo = 0;   s_end = 64;      }
            else             { s_lo = tau; s_end = 64;      }

            const float* hrow = sH + lf * 145 + 8;   // hrow[-8..136] valid
            const float* nrow = sN + lf * 65;

            // carried scalars: hc[q] = h[x+1+q], q=0..6, where x = t0 - sb
            float hc[7];
            {
                const int x0 = t0 - s_lo;
                #pragma unroll
                for (int q = 0; q < 7; ++q) hc[q] = hrow[x0 + 1 + q];
            }
            for (int sb = s_lo; sb < s_end; sb += 8) {
                const int x = t0 - sb;
                float hw[8];                         // hw[j] = h[x-7+j]
                #pragma unroll
                for (int j = 0; j < 8; ++j) hw[j] = hrow[x - 7 + j];

                // R[idx] = (h[x-6+idx], h[x-7+idx]), idx = 0..13
                u64 R[14];
                #pragma unroll
                for (int idx = 0; idx < 7; ++idx) R[idx] = pk2(hw[idx + 1], hw[idx]);
                R[7] = pk2(hc[0], hw[7]);
                #pragma unroll
                for (int idx = 8; idx < 14; ++idx) R[idx] = pk2(hc[idx - 7], hc[idx - 8]);

                u64 nA[4];                           // (n[s], n[s+1])
                #pragma unroll
                for (int u = 0; u < 4; ++u)
                    nA[u] = pk2(nrow[sb + 2 * u], nrow[sb + 2 * u + 1]);

                #pragma unroll
                for (int u = 0; u < 4; ++u)
                    #pragma unroll
                    for (int i = 0; i < 8; ++i)
                        ffma2(acc2[i], nA[u], R[i - 2 * u + 6]);

                #pragma unroll
                for (int q = 0; q < 7; ++q) hc[q] = hw[q];   // carry for x' = x-8
            }
        }
    }

    // each (g, hb, tau) tile of 8 samples owned by exactly one thread
    long p0 = (long)g * 2048 + (long)hb * 64 + tau;
    if (p0 < outlen) {   // outlen, p0 multiples of 8 -> full tile in-bounds
        float o[8];
        #pragma unroll
        for (int i = 0; i < 8; ++i) {
            float lo, hi; upk2(acc2[i], lo, hi);
            o[i] = lo + hi;
        }
        float* op = out + (long)b * outlen + p0;
        reinterpret_cast<float4*>(op)[0] = make_float4(o[0], o[1], o[2], o[3]);
        reinterpret_cast<float4*>(op)[1] = make_float4(o[4], o[5], o[6], o[7]);
    }
}

extern "C" void kernel_launch(void* const* d_in, const int* in_sizes, int n_in,
                              void* d_out, int out_size)
{
    const float* d_filter = (const float*)d_in[0];   // [B, F, 65]
    const float* d_noise  = (const float*)d_in[1];   // [B, F, 64]
    float* d_o = (float*)d_out;                      // [B, (F-1)*64 + 192]

    const long nframes = (long)in_sizes[0] / 65;     // B*F
    const long B = ((long)out_size - 64 * nframes) / 128;
    const int  F = (int)(nframes / B);
    const long outlen = (long)(F - 1) * 64 + 192;
    const int  G = (int)((outlen + 2047) / 2048);

    dim3 grid((unsigned)G, (unsigned)B);
    filtered_noise_kernel<<<grid, THREADS>>>(d_filter, d_noise, d_o, F, outlen);
}

// round 5
// speedup vs baseline: 1.0397x; 1.0016x over previous
#include <cuda_runtime.h>

// FilteredNoise: per-frame zero-phase FIR synthesis from real spectrum + OLA.
//   ir[n]  = (1/129)(X[0] + 2 sum_{k=1..64} X[k] cos(2pi k n / 129)),  ir symmetric
//   h[64-n] = ir[n]*win[64-n], h[64+n] = ir[n]*win[64+n]   (win = periodic Hann 129)
//   out[b, f*64 + t] += GAIN * sum_s n2[s] h[t-s]
//
// Each CTA owns 2048 output samples (32 hop blocks) of one batch row and the
// 34 frames (32 + 2 history) contributing to them -> every output sample is
// written exactly once. GAIN and irfft scaling are folded into X at load.
//
// Phase A: Chebyshev recurrence for cos(2pi k n/129) (no table gathers, no mod),
//          8 frames x 4 n register tile, packed fma.rn.f32x2 over frame pairs.
// Phase B: FIR conv with fma.rn.f32x2 over step pairs:
//          acc2_i += (n[s], n[s+1]) .* (h[t-s], h[t-s-1]); horizontal add at end.

#define THREADS 256
typedef unsigned long long u64;

__device__ __forceinline__ u64 pk2(float lo, float hi) {
    u64 r; asm("mov.b64 %0, {%1, %2};" : "=l"(r) : "f"(lo), "f"(hi)); return r;
}
__device__ __forceinline__ void upk2(u64 v, float& lo, float& hi) {
    asm("mov.b64 {%0, %1}, %2;" : "=f"(lo), "=f"(hi) : "l"(v));
}
__device__ __forceinline__ void ffma2(u64& d, u64 a, u64 b) {
    asm("fma.rn.f32x2 %0, %1, %2, %0;" : "+l"(d) : "l"(a), "l"(b));
}

__global__ __launch_bounds__(THREADS)
void filtered_noise_kernel(const float* __restrict__ filt,
                           const float* __restrict__ noise,
                           float* __restrict__ out,
                           int F, long outlen)
{
    // sXT[k][lf]: 65 x 36 (frames padded 34->36, even stride for u64 pairs)
    // sH [lf][m]: 34 x 145, rows: 8 zeros | h[0..128] | 8 zeros
    // sN [lf][s]: 34 x 65 (odd stride: conflict-free across lanes)
    __shared__ __align__(16) float sXT[65 * 36];
    __shared__ float sH[34 * 145];
    __shared__ float sN[34 * 65];

    const int tid = threadIdx.x;
    const int g   = blockIdx.x;             // group of 32 hop blocks
    const int b   = blockIdx.y;
    const long base_f = (long)g * 32 - 2;   // global frame of local frame 0

    const float* fb = filt  + (long)b * F * 65;
    const float* nb = noise + (long)b * F * 64;

    // ---- fills ----
    // sXT: lf fast -> conflict-free STS (LDG is strided; L2/DRAM have headroom)
    for (int i = tid; i < 65 * 36; i += THREADS) {
        int k = i / 36, lf = i - k * 36;
        long f = base_f + lf;
        float v = 0.0f;
        if (lf < 34 && f >= 0 && f < F) v = fb[f * 65 + k];
        float s = (k == 0) ? (0.01f / 129.0f) : (0.02f / 129.0f);
        sXT[i] = v * s;
    }
    // zero only the sH pads (phase A writes h[0..128] fully for all 34 rows)
    for (int i = tid; i < 34 * 16; i += THREADS) {
        int lf = i >> 4, j = i & 15;
        sH[lf * 145 + (j < 8 ? j : 129 + j)] = 0.0f;
    }
    for (int i = tid; i < 34 * 64; i += THREADS) {
        int lf = i >> 6, s = i & 63;
        long f = base_f + lf;
        float v = 0.5f;                     // -> n2 = 0 when frame invalid
        if (f >= 0 && f < F) v = nb[f * 64 + s];
        sN[lf * 65 + s] = 2.0f * v - 1.0f;
    }
    __syncthreads();

    // ---- Phase A: ir[n] via Chebyshev recurrence, 8 frames x 4 n / thread ----
    if (tid < 85) {
        const int ft = tid % 5;             // frames 8ft..8ft+7 (pairs 4ft..4ft+3)
        const int nt = tid / 5;             // n = 4nt..4nt+3 (n>64 discarded)

        float c[4], cp[4], coef[4];
        #pragma unroll
        for (int i = 0; i < 4; ++i) {
            float c1 = cospif((float)(2 * (4 * nt + i)) / 129.0f);
            coef[i] = 2.0f * c1;
            c[i]  = 1.0f;    // cos(0 * theta)
            cp[i] = c1;      // cos(-theta)
        }

        u64 acc[4][4];
        #pragma unroll
        for (int p = 0; p < 4; ++p)
            #pragma unroll
            for (int i = 0; i < 4; ++i) acc[p][i] = 0ull;

        const u64* xrow = (const u64*)(sXT + 8 * ft);   // 18 u64 per k-row
        #pragma unroll 5
        for (int k = 0; k < 65; ++k) {
            u64 x0 = xrow[k * 18 + 0];
            u64 x1 = xrow[k * 18 + 1];
            u64 x2 = xrow[k * 18 + 2];
            u64 x3 = xrow[k * 18 + 3];
            #pragma unroll
            for (int i = 0; i < 4; ++i) {
                u64 cc = pk2(c[i], c[i]);
                ffma2(acc[0][i], x0, cc);
                ffma2(acc[1][i], x1, cc);
                ffma2(acc[2][i], x2, cc);
                ffma2(acc[3][i], x3, cc);
                float cn = fmaf(coef[i], c[i], -cp[i]);   // cos((k+1)theta)
                cp[i] = c[i]; c[i] = cn;
            }
        }

        #pragma unroll
        for (int i = 0; i < 4; ++i) {
            int n = 4 * nt + i;
            if (n <= 64) {
                float w1 = 0.5f - 0.5f * cospif((float)(2 * (64 - n)) / 129.0f);
                float w2 = 0.5f - 0.5f * cospif((float)(2 * (64 + n)) / 129.0f);
                #pragma unroll
                for (int p = 0; p < 4; ++p) {
                    float ir0, ir1; upk2(acc[p][i], ir0, ir1);
                    int lf = 8 * ft + 2 * p;
                    if (lf < 34) {
                        float* r0 = sH + lf * 145 + 8;
                        r0[64 - n] = ir0 * w1;
                        r0[64 + n] = ir0 * w2;
                    }
                    if (lf + 1 < 34) {
                        float* r1 = sH + (lf + 1) * 145 + 8;
                        r1[64 - n] = ir1 * w1;
                        r1[64 + n] = ir1 * w2;
                    }
                }
            }
        }
    }
    __syncthreads();

    // ---- Phase B: FIR conv + OLA. warp -> tau (uniform), lane -> hop block ----
    const int w    = tid >> 5;
    const int lane = tid & 31;
    const int tau  = w << 3;        // 0,8,...,56
    const int hb   = lane;          // local hop block 0..31

    u64 acc2[8];                    // acc2[i] halves: (even-s part, odd-s part)
    #pragma unroll
    for (int i = 0; i < 8; ++i) acc2[i] = 0ull;

    #pragma unroll
    for (int d = 0; d < 3; ++d) {   // frame offset: f = hopblock - d
        long fglob = (long)g * 32 + hb - d;
        if (fglob >= 0 && fglob < F) {
            const int lf = hb - d + 2;            // local frame row, in [0,33]
            const int t0 = tau + (d << 6);        // frame-local output base (mult of 8)
            int s_lo, s_end;                      // multiples of 8
            if (d == 0)      { s_lo = 0;   s_end = tau + 8; }
            else if (d == 1) { s_lo = 0;   s_end = 64;      }
            else             { s_lo = tau; s_end = 64;      }

            const float* hrow = sH + lf * 145 + 8;   // hrow[-8..136] valid
            const float* nrow = sN + lf * 65;

            // carried scalars: hc[q] = h[x+1+q], q=0..6, where x = t0 - sb
            float hc[7];
            {
                const int x0 = t0 - s_lo;
                #pragma unroll
                for (int q = 0; q < 7; ++q) hc[q] = hrow[x0 + 1 + q];
            }
            for (int sb = s_lo; sb < s_end; sb += 8) {
                const int x = t0 - sb;
                float hw[8];                         // hw[j] = h[x-7+j]
                #pragma unroll
                for (int j = 0; j < 8; ++j) hw[j] = hrow[x - 7 + j];

                // R[idx] = (h[x-6+idx], h[x-7+idx]), idx = 0..13
                u64 R[14];
                #pragma unroll
                for (int idx = 0; idx < 7; ++idx) R[idx] = pk2(hw[idx + 1], hw[idx]);
                R[7] = pk2(hc[0], hw[7]);
                #pragma unroll
                for (int idx = 8; idx < 14; ++idx) R[idx] = pk2(hc[idx - 7], hc[idx - 8]);

                u64 nA[4];                           // (n[s], n[s+1])
                #pragma unroll
                for (int u = 0; u < 4; ++u)
                    nA[u] = pk2(nrow[sb + 2 * u], nrow[sb + 2 * u + 1]);

                #pragma unroll
                for (int u = 0; u < 4; ++u)
                    #pragma unroll
                    for (int i = 0; i < 8; ++i)
                        ffma2(acc2[i], nA[u], R[i - 2 * u + 6]);

                #pragma unroll
                for (int q = 0; q < 7; ++q) hc[q] = hw[q];   // carry for x' = x-8
            }
        }
    }

    // each (g, hb, tau) tile of 8 samples owned by exactly one thread
    long p0 = (long)g * 2048 + (long)hb * 64 + tau;
    if (p0 < outlen) {   // outlen, p0 multiples of 8 -> full tile in-bounds
        float o[8];
        #pragma unroll
        for (int i = 0; i < 8; ++i) {
            float lo, hi; upk2(acc2[i], lo, hi);
            o[i] = lo + hi;
        }
        float* op = out + (long)b * outlen + p0;
        reinterpret_cast<float4*>(op)[0] = make_float4(o[0], o[1], o[2], o[3]);
        reinterpret_cast<float4*>(op)[1] = make_float4(o[4], o[5], o[6], o[7]);
    }
}

extern "C" void kernel_launch(void* const* d_in, const int* in_sizes, int n_in,
                              void* d_out, int out_size)
{
    const float* d_filter = (const float*)d_in[0];   // [B, F, 65]
    const float* d_noise  = (const float*)d_in[1];   // [B, F, 64]
    float* d_o = (float*)d_out;                      // [B, (F-1)*64 + 192]

    const long nframes = (long)in_sizes[0] / 65;     // B*F
    const long B = ((long)out_size - 64 * nframes) / 128;
    const int  F = (int)(nframes / B);
    const long outlen = (long)(F - 1) * 64 + 192;
    const int  G = (int)((outlen + 2047) / 2048);

    dim3 grid((unsigned)G, (unsigned)B);
    filtered_noise_kernel<<<grid, THREADS>>>(d_filter, d_noise, d_o, F, outlen);
}

// round 6
// speedup vs baseline: 1.0399x; 1.0002x over previous
#include <cuda_runtime.h>

// FilteredNoise: per-frame zero-phase FIR synthesis from real spectrum + OLA.
//   ir[n]  = (1/129)(X[0] + 2 sum_{k=1..64} X[k] cos(2pi k n / 129)),  ir symmetric
//   h[64-n] = ir[n]*win[64-n], h[64+n] = ir[n]*win[64+n]   (win = periodic Hann 129)
//   out[b, f*64 + t] += GAIN * sum_s n2[s] h[t-s]
//
// Each CTA owns 2048 output samples (32 hop blocks) of one batch row and the
// 34 frames (32 + 2 history) contributing to them -> every output sample is
// written exactly once. GAIN and irfft scaling are folded into X at load.
//
// Phase A: Chebyshev recurrence for cos(2pi k n/129) (no table gathers, no mod),
//          8 frames x 4 n register tile, packed fma.rn.f32x2 over frame pairs.
// Phase B: FIR conv with fma.rn.f32x2 over step pairs:
//          acc2_i += (n[s], n[s+1]) .* (h[t-s], h[t-s-1]); horizontal add at end.

#define THREADS 256
typedef unsigned long long u64;

__device__ __forceinline__ u64 pk2(float lo, float hi) {
    u64 r; asm("mov.b64 %0, {%1, %2};" : "=l"(r) : "f"(lo), "f"(hi)); return r;
}
__device__ __forceinline__ void upk2(u64 v, float& lo, float& hi) {
    asm("mov.b64 {%0, %1}, %2;" : "=f"(lo), "=f"(hi) : "l"(v));
}
__device__ __forceinline__ void ffma2(u64& d, u64 a, u64 b) {
    asm("fma.rn.f32x2 %0, %1, %2, %0;" : "+l"(d) : "l"(a), "l"(b));
}

__global__ __launch_bounds__(THREADS)
void filtered_noise_kernel(const float* __restrict__ filt,
                           const float* __restrict__ noise,
                           float* __restrict__ out,
                           int F, long outlen)
{
    // sXT[k][lf]: 65 x 36 (frames padded 34->36, even stride for u64 pairs)
    // sH [lf][m]: 34 x 145, rows: 8 zeros | h[0..128] | 8 zeros
    // sN [lf][s]: 34 x 65 (odd stride: conflict-free across lanes)
    __shared__ __align__(16) float sXT[65 * 36];
    __shared__ float sH[34 * 145];
    __shared__ float sN[34 * 65];

    const int tid = threadIdx.x;
    const int g   = blockIdx.x;             // group of 32 hop blocks
    const int b   = blockIdx.y;
    const long base_f = (long)g * 32 - 2;   // global frame of local frame 0

    const float* fb = filt  + (long)b * F * 65;
    const float* nb = noise + (long)b * F * 64;

    // ---- fills ----
    // sXT: lf fast -> conflict-free STS (LDG is strided; L2/DRAM have headroom)
    for (int i = tid; i < 65 * 36; i += THREADS) {
        int k = i / 36, lf = i - k * 36;
        long f = base_f + lf;
        float v = 0.0f;
        if (lf < 34 && f >= 0 && f < F) v = fb[f * 65 + k];
        float s = (k == 0) ? (0.01f / 129.0f) : (0.02f / 129.0f);
        sXT[i] = v * s;
    }
    // zero only the sH pads (phase A writes h[0..128] fully for all 34 rows)
    for (int i = tid; i < 34 * 16; i += THREADS) {
        int lf = i >> 4, j = i & 15;
        sH[lf * 145 + (j < 8 ? j : 129 + j)] = 0.0f;
    }
    for (int i = tid; i < 34 * 64; i += THREADS) {
        int lf = i >> 6, s = i & 63;
        long f = base_f + lf;
        float v = 0.5f;                     // -> n2 = 0 when frame invalid
        if (f >= 0 && f < F) v = nb[f * 64 + s];
        sN[lf * 65 + s] = 2.0f * v - 1.0f;
    }
    __syncthreads();

    // ---- Phase A: ir[n] via Chebyshev recurrence, 8 frames x 4 n / thread ----
    if (tid < 85) {
        const int ft = tid % 5;             // frames 8ft..8ft+7 (pairs 4ft..4ft+3)
        const int nt = tid / 5;             // n = 4nt..4nt+3 (n>64 discarded)

        float c[4], cp[4], coef[4];
        #pragma unroll
        for (int i = 0; i < 4; ++i) {
            float c1 = cospif((float)(2 * (4 * nt + i)) / 129.0f);
            coef[i] = 2.0f * c1;
            c[i]  = 1.0f;    // cos(0 * theta)
            cp[i] = c1;      // cos(-theta)
        }

        u64 acc[4][4];
        #pragma unroll
        for (int p = 0; p < 4; ++p)
            #pragma unroll
            for (int i = 0; i < 4; ++i) acc[p][i] = 0ull;

        const u64* xrow = (const u64*)(sXT + 8 * ft);   // 18 u64 per k-row
        #pragma unroll 5
        for (int k = 0; k < 65; ++k) {
            u64 x0 = xrow[k * 18 + 0];
            u64 x1 = xrow[k * 18 + 1];
            u64 x2 = xrow[k * 18 + 2];
            u64 x3 = xrow[k * 18 + 3];
            #pragma unroll
            for (int i = 0; i < 4; ++i) {
                u64 cc = pk2(c[i], c[i]);
                ffma2(acc[0][i], x0, cc);
                ffma2(acc[1][i], x1, cc);
                ffma2(acc[2][i], x2, cc);
                ffma2(acc[3][i], x3, cc);
                float cn = fmaf(coef[i], c[i], -cp[i]);   // cos((k+1)theta)
                cp[i] = c[i]; c[i] = cn;
            }
        }

        #pragma unroll
        for (int i = 0; i < 4; ++i) {
            int n = 4 * nt + i;
            if (n <= 64) {
                float w1 = 0.5f - 0.5f * cospif((float)(2 * (64 - n)) / 129.0f);
                float w2 = 0.5f - 0.5f * cospif((float)(2 * (64 + n)) / 129.0f);
                #pragma unroll
                for (int p = 0; p < 4; ++p) {
                    float ir0, ir1; upk2(acc[p][i], ir0, ir1);
                    int lf = 8 * ft + 2 * p;
                    if (lf < 34) {
                        float* r0 = sH + lf * 145 + 8;
                        r0[64 - n] = ir0 * w1;
                        r0[64 + n] = ir0 * w2;
                    }
                    if (lf + 1 < 34) {
                        float* r1 = sH + (lf + 1) * 145 + 8;
                        r1[64 - n] = ir1 * w1;
                        r1[64 + n] = ir1 * w2;
                    }
                }
            }
        }
    }
    __syncthreads();

    // ---- Phase B: FIR conv + OLA. warp -> tau (uniform), lane -> hop block ----
    const int w    = tid >> 5;
    const int lane = tid & 31;
    const int tau  = w << 3;        // 0,8,...,56
    const int hb   = lane;          // local hop block 0..31

    u64 acc2[8];                    // acc2[i] halves: (even-s part, odd-s part)
    #pragma unroll
    for (int i = 0; i < 8; ++i) acc2[i] = 0ull;

    #pragma unroll
    for (int d = 0; d < 3; ++d) {   // frame offset: f = hopblock - d
        long fglob = (long)g * 32 + hb - d;
        if (fglob >= 0 && fglob < F) {
            const int lf = hb - d + 2;            // local frame row, in [0,33]
            const int t0 = tau + (d << 6);        // frame-local output base (mult of 8)
            int s_lo, s_end;                      // multiples of 8
            if (d == 0)      { s_lo = 0;   s_end = tau + 8; }
            else if (d == 1) { s_lo = 0;   s_end = 64;      }
            else             { s_lo = tau; s_end = 64;      }

            const float* hrow = sH + lf * 145 + 8;   // hrow[-8..136] valid
            const float* nrow = sN + lf * 65;

            // carried scalars: hc[q] = h[x+1+q], q=0..6, where x = t0 - sb
            float hc[7];
            {
                const int x0 = t0 - s_lo;
                #pragma unroll
                for (int q = 0; q < 7; ++q) hc[q] = hrow[x0 + 1 + q];
            }
            for (int sb = s_lo; sb < s_end; sb += 8) {
                const int x = t0 - sb;
                float hw[8];                         // hw[j] = h[x-7+j]
                #pragma unroll
                for (int j = 0; j < 8; ++j) hw[j] = hrow[x - 7 + j];

                // R[idx] = (h[x-6+idx], h[x-7+idx]), idx = 0..13
                u64 R[14];
                #pragma unroll
                for (int idx = 0; idx < 7; ++idx) R[idx] = pk2(hw[idx + 1], hw[idx]);
                R[7] = pk2(hc[0], hw[7]);
                #pragma unroll
                for (int idx = 8; idx < 14; ++idx) R[idx] = pk2(hc[idx - 7], hc[idx - 8]);

                u64 nA[4];                           // (n[s], n[s+1])
                #pragma unroll
                for (int u = 0; u < 4; ++u)
                    nA[u] = pk2(nrow[sb + 2 * u], nrow[sb + 2 * u + 1]);

                #pragma unroll
                for (int u = 0; u < 4; ++u)
                    #pragma unroll
                    for (int i = 0; i < 8; ++i)
                        ffma2(acc2[i], nA[u], R[i - 2 * u + 6]);

                #pragma unroll
                for (int q = 0; q < 7; ++q) hc[q] = hw[q];   // carry for x' = x-8
            }
        }
    }

    // each (g, hb, tau) tile of 8 samples owned by exactly one thread
    long p0 = (long)g * 2048 + (long)hb * 64 + tau;
    if (p0 < outlen) {   // outlen, p0 multiples of 8 -> full tile in-bounds
        float o[8];
        #pragma unroll
        for (int i = 0; i < 8; ++i) {
            float lo, hi; upk2(acc2[i], lo, hi);
            o[i] = lo + hi;
        }
        float* op = out + (long)b * outlen + p0;
        reinterpret_cast<float4*>(op)[0] = make_float4(o[0], o[1], o[2], o[3]);
        reinterpret_cast<float4*>(op)[1] = make_float4(o[4], o[5], o[6], o[7]);
    }
}

extern "C" void kernel_launch(void* const* d_in, const int* in_sizes, int n_in,
                              void* d_out, int out_size)
{
    const float* d_filter = (const float*)d_in[0];   // [B, F, 65]
    const float* d_noise  = (const float*)d_in[1];   // [B, F, 64]
    float* d_o = (float*)d_out;                      // [B, (F-1)*64 + 192]

    const long nframes = (long)in_sizes[0] / 65;     // B*F
    const long B = ((long)out_size - 64 * nframes) / 128;
    const int  F = (int)(nframes / B);
    const long outlen = (long)(F - 1) * 64 + 192;
    const int  G = (int)((outlen + 2047) / 2048);

    dim3 grid((unsigned)G, (unsigned)B);
    filtered_noise_kernel<<<grid, THREADS>>>(d_filter, d_noise, d_o, F, outlen);
}

// round 7
// speedup vs baseline: 1.1734x; 1.1283x over previous
#include <cuda_runtime.h>

// FilteredNoise: per-frame zero-phase FIR synthesis from real spectrum + OLA.
//   ir[n]  = (1/129)(X[0] + 2 sum_{k=1..64} X[k] cos(2pi k n / 129)),  ir symmetric
//   h[64-n] = ir[n]*win[64-n], h[64+n] = ir[n]*win[64+n]   (win = periodic Hann 129)
//   out[b, f*64 + t] += GAIN * sum_s n2[s] h[t-s]
//
// CTA owns 2048 output samples (32 hop blocks) of one batch row; 34 frames
// (32 + 2 history) contribute; every output written exactly once.
//
// Phase A (warp-uniform): lanes <-> IR-index pair (n, n+32) with a shared
//   Chebyshev cos recurrence; 5 frames per warp (frame dim padded to 40 so all
//   8 warps run identical work); X[f][k] read as LDS broadcast. Scaling
//   (GAIN, 1/129, x2 for k>0) folded into the Hann weights.
// Phase B: FIR conv with fma.rn.f32x2 over step pairs; h window via 2xLDS.128
//   (row stride 148 = 37 odd granules, conflict-free), noise pairs via
//   2xLDS.128 reinterpreted directly as packed (n[s],n[s+1]) u64 operands.

#define THREADS 256
#define SHROW 148   // sH row stride (floats): 37 x 16B, odd -> LDS.128 conflict-free
#define SNROW 68    // sN row stride (floats): 17 x 16B, odd -> LDS.128 conflict-free
typedef unsigned long long u64;

__device__ __forceinline__ u64 pk2(float lo, float hi) {
    u64 r; asm("mov.b64 %0, {%1, %2};" : "=l"(r) : "f"(lo), "f"(hi)); return r;
}
__device__ __forceinline__ void upk2(u64 v, float& lo, float& hi) {
    asm("mov.b64 {%0, %1}, %2;" : "=f"(lo), "=f"(hi) : "l"(v));
}
__device__ __forceinline__ void ffma2(u64& d, u64 a, u64 b) {
    asm("fma.rn.f32x2 %0, %1, %2, %0;" : "+l"(d) : "l"(a), "l"(b));
}

__global__ __launch_bounds__(THREADS, 4)
void filtered_noise_kernel(const float* __restrict__ filt,
                           const float* __restrict__ noise,
                           float* __restrict__ out,
                           int F, long outlen)
{
    __shared__ float sX[40 * 65];                    // raw X, frames padded 34->40
    __shared__ __align__(16) float sH[40 * SHROW];   // rows: 8 pad | h[0..128] | pad
    __shared__ __align__(16) float sN[34 * SNROW];   // n2 = 2*noise-1

    const int tid  = threadIdx.x;
    const int w    = tid >> 5;
    const int lane = tid & 31;
    const int g    = blockIdx.x;             // group of 32 hop blocks
    const int b    = blockIdx.y;
    const long base_f = (long)g * 32 - 2;    // global frame of local frame 0

    const float* fb = filt  + (long)b * F * 65;
    const float* nb = noise + (long)b * F * 64;

    // ---- fills ----
    for (int i = tid; i < 40 * 65; i += THREADS) {   // coalesced raw copy
        int lf = i / 65;
        int k  = i - lf * 65;
        long f = base_f + lf;
        sX[i] = (lf < 34 && f >= 0 && f < F) ? fb[f * 65 + k] : 0.0f;
    }
    for (int i = tid; i < 34 * 16; i += THREADS) {   // sN via float4
        int lf = i >> 4, j = i & 15;
        long f = base_f + lf;
        float4 v = make_float4(0.5f, 0.5f, 0.5f, 0.5f);
        if (f >= 0 && f < F) v = ((const float4*)(nb + f * 64))[j];
        float4 r = make_float4(2.0f * v.x - 1.0f, 2.0f * v.y - 1.0f,
                               2.0f * v.z - 1.0f, 2.0f * v.w - 1.0f);
        *(float4*)(sN + lf * SNROW + 4 * j) = r;
    }
    for (int i = tid; i < 34 * 16; i += THREADS) {   // sH zero pads (rows 0..33)
        int lf = i >> 4, j = i & 15;
        sH[lf * SHROW + (j < 8 ? j : 129 + j)] = 0.0f;   // 0..7 and 137..144
    }
    __syncthreads();

    // ---- Phase A: warp-uniform IR synthesis ----
    {
        const int n0 = lane + 1;                     // 1..32
        const int n1 = lane + 33;                    // 33..64
        float u0 = cospif((float)(2 * n0) / 129.0f); // cos(1*theta0)
        float u1 = cospif((float)(2 * n1) / 129.0f);
        const float k20 = 2.0f * u0, k21 = 2.0f * u1;
        float p0 = 1.0f, p1 = 1.0f;                  // cos(0*theta)

        const int fs = 5 * w;                        // frames fs..fs+4 (pad rows ok)
        const float* xp = sX + fs * 65;
        u64 acc[5];
        #pragma unroll
        for (int j = 0; j < 5; ++j) {
            float h0 = 0.5f * xp[j * 65];            // k=0 term (halved)
            acc[j] = pk2(h0, h0);
        }
        for (int k = 1; k < 65; ++k) {
            u64 c2 = pk2(u0, u1);
            #pragma unroll
            for (int j = 0; j < 5; ++j) {
                float x = xp[j * 65 + k];            // LDS broadcast
                ffma2(acc[j], pk2(x, x), c2);
            }
            float t0 = fmaf(k20, u0, -p0); p0 = u0; u0 = t0;
            float t1 = fmaf(k21, u1, -p1); p1 = u1; u1 = t1;
        }
        const float S = 0.02f / 129.0f;              // GAIN * 2 / 129
        float w1a = (0.5f - 0.5f * cospif((float)(2 * (64 - n0)) / 129.0f)) * S;
        float w2a = (0.5f - 0.5f * cospif((float)(2 * (64 + n0)) / 129.0f)) * S;
        float w1b = (0.5f - 0.5f * cospif((float)(2 * (64 - n1)) / 129.0f)) * S;
        float w2b = (0.5f - 0.5f * cospif((float)(2 * (64 + n1)) / 129.0f)) * S;
        #pragma unroll
        for (int j = 0; j < 5; ++j) {
            float i0, i1; upk2(acc[j], i0, i1);
            float* hr = sH + (fs + j) * SHROW + 8;
            hr[64 - n0] = i0 * w1a;  hr[64 + n0] = i0 * w2a;
            hr[64 - n1] = i1 * w1b;  hr[64 + n1] = i1 * w2b;
        }
    }
    // n = 0 leftover: h[64] = win[64]*S * (0.5 X0 + sum_k Xk)
    if (tid < 34) {
        const float* xr = sX + tid * 65;
        float s0 = 0.5f * xr[0], s1 = 0.0f, s2 = 0.0f, s3 = 0.0f;
        #pragma unroll 4
        for (int k = 1; k < 65; k += 4) {
            s0 += xr[k]; s1 += xr[k + 1]; s2 += xr[k + 2]; s3 += xr[k + 3];
        }
        float win64s = (0.5f - 0.5f * cospif(128.0f / 129.0f)) * (0.02f / 129.0f);
        sH[tid * SHROW + 8 + 64] = (s0 + s1 + s2 + s3) * win64s;
    }
    __syncthreads();

    // ---- Phase B: FIR conv + OLA. warp -> tau (uniform), lane -> hop block ----
    const int tau = w << 3;        // 0,8,...,56
    const int hb  = lane;          // local hop block 0..31

    u64 acc2[8];                   // halves: (even-s part, odd-s part)
    #pragma unroll
    for (int i = 0; i < 8; ++i) acc2[i] = 0ull;

    #pragma unroll
    for (int d = 0; d < 3; ++d) {  // frame offset: f = hopblock - d
        long fglob = (long)g * 32 + hb - d;
        if (fglob >= 0 && fglob < F) {
            const int lf = hb - d + 2;           // local frame row, in [0,33]
            const int t0 = tau + (d << 6);       // frame-local output base
            const int s_lo  = (d == 2) ? tau : 0;
            const int s_end = (d == 0) ? tau + 8 : 64;

            const float* hrow = sH + lf * SHROW + 8;   // hrow[-8..136] valid
            const float* nrow = sN + lf * SNROW;

            int x = t0 - s_lo;                   // multiple of 8
            float hc[8];                         // hc[q] = h[x + q]
            {
                float4 a = *(const float4*)(hrow + x);
                float4 b = *(const float4*)(hrow + x + 4);
                hc[0] = a.x; hc[1] = a.y; hc[2] = a.z; hc[3] = a.w;
                hc[4] = b.x; hc[5] = b.y; hc[6] = b.z; hc[7] = b.w;
            }
            for (int sb = s_lo; sb < s_end; sb += 8) {
                float4 La = *(const float4*)(hrow + x - 8);   // h[x-8..x-5]
                float4 Lb = *(const float4*)(hrow + x - 4);   // h[x-4..x-1]
                float L[8] = {La.x, La.y, La.z, La.w, Lb.x, Lb.y, Lb.z, Lb.w};

                // R[idx] = (lo=h[m+1], hi=h[m]), m = x-7+idx
                u64 R[14];
                #pragma unroll
                for (int idx = 0; idx < 6; ++idx) R[idx] = pk2(L[idx + 2], L[idx + 1]);
                R[6] = pk2(hc[0], L[7]);
                #pragma unroll
                for (int idx = 7; idx < 14; ++idx) R[idx] = pk2(hc[idx - 6], hc[idx - 7]);

                // noise pairs straight from memory: lo = n[s], hi = n[s+1]
                ulonglong2 nn0 = *(const ulonglong2*)(nrow + sb);
                ulonglong2 nn1 = *(const ulonglong2*)(nrow + sb + 4);
                u64 nA[4] = {nn0.x, nn0.y, nn1.x, nn1.y};

                #pragma unroll
                for (int u = 0; u < 4; ++u)
                    #pragma unroll
                    for (int i = 0; i < 8; ++i)
                        ffma2(acc2[i], nA[u], R[i - 2 * u + 6]);

                #pragma unroll
                for (int q = 0; q < 8; ++q) hc[q] = L[q];     // carry: h[x-8+q]
                x -= 8;
            }
        }
    }

    // each (g, hb, tau) tile of 8 samples owned by exactly one thread
    long p0 = (long)g * 2048 + (long)hb * 64 + tau;
    if (p0 < outlen) {   // outlen, p0 multiples of 8 -> full tile in-bounds
        float o[8];
        #pragma unroll
        for (int i = 0; i < 8; ++i) {
            float lo, hi; upk2(acc2[i], lo, hi);
            o[i] = lo + hi;
        }
        float* op = out + (long)b * outlen + p0;
        reinterpret_cast<float4*>(op)[0] = make_float4(o[0], o[1], o[2], o[3]);
        reinterpret_cast<float4*>(op)[1] = make_float4(o[4], o[5], o[6], o[7]);
    }
}

extern "C" void kernel_launch(void* const* d_in, const int* in_sizes, int n_in,
                              void* d_out, int out_size)
{
    const float* d_filter = (const float*)d_in[0];   // [B, F, 65]
    const float* d_noise  = (const float*)d_in[1];   // [B, F, 64]
    float* d_o = (float*)d_out;                      // [B, (F-1)*64 + 192]

    const long nframes = (long)in_sizes[0] / 65;     // B*F
    const long B = ((long)out_size - 64 * nframes) / 128;
    const int  F = (int)(nframes / B);
    const long outlen = (long)(F - 1) * 64 + 192;
    const int  G = (int)((outlen + 2047) / 2048);

    dim3 grid((unsigned)G, (unsigned)B);
    filtered_noise_kernel<<<grid, THREADS>>>(d_filter, d_noise, d_o, F, outlen);
}

// round 8
// speedup vs baseline: 1.1767x; 1.0028x over previous
#include <cuda_runtime.h>

// FilteredNoise: per-frame zero-phase FIR synthesis from real spectrum + OLA.
//   ir[n]  = (1/129)(X[0] + 2 sum_{k=1..64} X[k] cos(2pi k n / 129)),  ir symmetric
//   h[64-n] = ir[n]*win[64-n], h[64+n] = ir[n]*win[64+n]   (win = periodic Hann 129)
//   out[b, f*64 + t] += GAIN * sum_s n2[s] h[t-s]
//
// CTA owns 2048 output samples (32 hop blocks) of one batch row; 34 frames
// (32 + 2 history) contribute; every output written exactly once.
//
// Phase A (warp-uniform): lanes <-> IR-index pair (n, n+32) with a shared
//   Chebyshev cos recurrence; 5 frames per warp (frame dim padded to 40 so all
//   8 warps run identical work); X[f][k] read as LDS broadcast. Scaling
//   (GAIN, 1/129, x2 for k>0) folded into the Hann weights.
// Phase B: FIR conv with fma.rn.f32x2 over step pairs; h window via 2xLDS.128
//   (row stride 148 = 37 odd granules, conflict-free), noise pairs via
//   2xLDS.128 reinterpreted directly as packed (n[s],n[s+1]) u64 operands.

#define THREADS 256
#define SHROW 148   // sH row stride (floats): 37 x 16B, odd -> LDS.128 conflict-free
#define SNROW 68    // sN row stride (floats): 17 x 16B, odd -> LDS.128 conflict-free
typedef unsigned long long u64;

__device__ __forceinline__ u64 pk2(float lo, float hi) {
    u64 r; asm("mov.b64 %0, {%1, %2};" : "=l"(r) : "f"(lo), "f"(hi)); return r;
}
__device__ __forceinline__ void upk2(u64 v, float& lo, float& hi) {
    asm("mov.b64 {%0, %1}, %2;" : "=f"(lo), "=f"(hi) : "l"(v));
}
__device__ __forceinline__ void ffma2(u64& d, u64 a, u64 b) {
    asm("fma.rn.f32x2 %0, %1, %2, %0;" : "+l"(d) : "l"(a), "l"(b));
}

__global__ __launch_bounds__(THREADS, 4)
void filtered_noise_kernel(const float* __restrict__ filt,
                           const float* __restrict__ noise,
                           float* __restrict__ out,
                           int F, long outlen)
{
    __shared__ float sX[40 * 65];                    // raw X, frames padded 34->40
    __shared__ __align__(16) float sH[40 * SHROW];   // rows: 8 pad | h[0..128] | pad
    __shared__ __align__(16) float sN[34 * SNROW];   // n2 = 2*noise-1

    const int tid  = threadIdx.x;
    const int w    = tid >> 5;
    const int lane = tid & 31;
    const int g    = blockIdx.x;             // group of 32 hop blocks
    const int b    = blockIdx.y;
    const long base_f = (long)g * 32 - 2;    // global frame of local frame 0

    const float* fb = filt  + (long)b * F * 65;
    const float* nb = noise + (long)b * F * 64;

    // ---- fills ----
    for (int i = tid; i < 40 * 65; i += THREADS) {   // coalesced raw copy
        int lf = i / 65;
        int k  = i - lf * 65;
        long f = base_f + lf;
        sX[i] = (lf < 34 && f >= 0 && f < F) ? fb[f * 65 + k] : 0.0f;
    }
    for (int i = tid; i < 34 * 16; i += THREADS) {   // sN via float4
        int lf = i >> 4, j = i & 15;
        long f = base_f + lf;
        float4 v = make_float4(0.5f, 0.5f, 0.5f, 0.5f);
        if (f >= 0 && f < F) v = ((const float4*)(nb + f * 64))[j];
        float4 r = make_float4(2.0f * v.x - 1.0f, 2.0f * v.y - 1.0f,
                               2.0f * v.z - 1.0f, 2.0f * v.w - 1.0f);
        *(float4*)(sN + lf * SNROW + 4 * j) = r;
    }
    for (int i = tid; i < 34 * 16; i += THREADS) {   // sH zero pads (rows 0..33)
        int lf = i >> 4, j = i & 15;
        sH[lf * SHROW + (j < 8 ? j : 129 + j)] = 0.0f;   // 0..7 and 137..144
    }
    __syncthreads();

    // ---- Phase A: warp-uniform IR synthesis ----
    {
        const int n0 = lane + 1;                     // 1..32
        const int n1 = lane + 33;                    // 33..64
        float u0 = cospif((float)(2 * n0) / 129.0f); // cos(1*theta0)
        float u1 = cospif((float)(2 * n1) / 129.0f);
        const float k20 = 2.0f * u0, k21 = 2.0f * u1;
        float p0 = 1.0f, p1 = 1.0f;                  // cos(0*theta)

        const int fs = 5 * w;                        // frames fs..fs+4 (pad rows ok)
        const float* xp = sX + fs * 65;
        u64 acc[5];
        #pragma unroll
        for (int j = 0; j < 5; ++j) {
            float h0 = 0.5f * xp[j * 65];            // k=0 term (halved)
            acc[j] = pk2(h0, h0);
        }
        for (int k = 1; k < 65; ++k) {
            u64 c2 = pk2(u0, u1);
            #pragma unroll
            for (int j = 0; j < 5; ++j) {
                float x = xp[j * 65 + k];            // LDS broadcast
                ffma2(acc[j], pk2(x, x), c2);
            }
            float t0 = fmaf(k20, u0, -p0); p0 = u0; u0 = t0;
            float t1 = fmaf(k21, u1, -p1); p1 = u1; u1 = t1;
        }
        const float S = 0.02f / 129.0f;              // GAIN * 2 / 129
        float w1a = (0.5f - 0.5f * cospif((float)(2 * (64 - n0)) / 129.0f)) * S;
        float w2a = (0.5f - 0.5f * cospif((float)(2 * (64 + n0)) / 129.0f)) * S;
        float w1b = (0.5f - 0.5f * cospif((float)(2 * (64 - n1)) / 129.0f)) * S;
        float w2b = (0.5f - 0.5f * cospif((float)(2 * (64 + n1)) / 129.0f)) * S;
        #pragma unroll
        for (int j = 0; j < 5; ++j) {
            float i0, i1; upk2(acc[j], i0, i1);
            float* hr = sH + (fs + j) * SHROW + 8;
            hr[64 - n0] = i0 * w1a;  hr[64 + n0] = i0 * w2a;
            hr[64 - n1] = i1 * w1b;  hr[64 + n1] = i1 * w2b;
        }
    }
    // n = 0 leftover: h[64] = win[64]*S * (0.5 X0 + sum_k Xk)
    if (tid < 34) {
        const float* xr = sX + tid * 65;
        float s0 = 0.5f * xr[0], s1 = 0.0f, s2 = 0.0f, s3 = 0.0f;
        #pragma unroll 4
        for (int k = 1; k < 65; k += 4) {
            s0 += xr[k]; s1 += xr[k + 1]; s2 += xr[k + 2]; s3 += xr[k + 3];
        }
        float win64s = (0.5f - 0.5f * cospif(128.0f / 129.0f)) * (0.02f / 129.0f);
        sH[tid * SHROW + 8 + 64] = (s0 + s1 + s2 + s3) * win64s;
    }
    __syncthreads();

    // ---- Phase B: FIR conv + OLA. warp -> tau (uniform), lane -> hop block ----
    const int tau = w << 3;        // 0,8,...,56
    const int hb  = lane;          // local hop block 0..31

    u64 acc2[8];                   // halves: (even-s part, odd-s part)
    #pragma unroll
    for (int i = 0; i < 8; ++i) acc2[i] = 0ull;

    #pragma unroll
    for (int d = 0; d < 3; ++d) {  // frame offset: f = hopblock - d
        long fglob = (long)g * 32 + hb - d;
        if (fglob >= 0 && fglob < F) {
            const int lf = hb - d + 2;           // local frame row, in [0,33]
            const int t0 = tau + (d << 6);       // frame-local output base
            const int s_lo  = (d == 2) ? tau : 0;
            const int s_end = (d == 0) ? tau + 8 : 64;

            const float* hrow = sH + lf * SHROW + 8;   // hrow[-8..136] valid
            const float* nrow = sN + lf * SNROW;

            int x = t0 - s_lo;                   // multiple of 8
            float hc[8];                         // hc[q] = h[x + q]
            {
                float4 a = *(const float4*)(hrow + x);
                float4 b = *(const float4*)(hrow + x + 4);
                hc[0] = a.x; hc[1] = a.y; hc[2] = a.z; hc[3] = a.w;
                hc[4] = b.x; hc[5] = b.y; hc[6] = b.z; hc[7] = b.w;
            }
            for (int sb = s_lo; sb < s_end; sb += 8) {
                float4 La = *(const float4*)(hrow + x - 8);   // h[x-8..x-5]
                float4 Lb = *(const float4*)(hrow + x - 4);   // h[x-4..x-1]
                float L[8] = {La.x, La.y, La.z, La.w, Lb.x, Lb.y, Lb.z, Lb.w};

                // R[idx] = (lo=h[m+1], hi=h[m]), m = x-7+idx
                u64 R[14];
                #pragma unroll
                for (int idx = 0; idx < 6; ++idx) R[idx] = pk2(L[idx + 2], L[idx + 1]);
                R[6] = pk2(hc[0], L[7]);
                #pragma unroll
                for (int idx = 7; idx < 14; ++idx) R[idx] = pk2(hc[idx - 6], hc[idx - 7]);

                // noise pairs straight from memory: lo = n[s], hi = n[s+1]
                ulonglong2 nn0 = *(const ulonglong2*)(nrow + sb);
                ulonglong2 nn1 = *(const ulonglong2*)(nrow + sb + 4);
                u64 nA[4] = {nn0.x, nn0.y, nn1.x, nn1.y};

                #pragma unroll
                for (int u = 0; u < 4; ++u)
                    #pragma unroll
                    for (int i = 0; i < 8; ++i)
                        ffma2(acc2[i], nA[u], R[i - 2 * u + 6]);

                #pragma unroll
                for (int q = 0; q < 8; ++q) hc[q] = L[q];     // carry: h[x-8+q]
                x -= 8;
            }
        }
    }

    // each (g, hb, tau) tile of 8 samples owned by exactly one thread
    long p0 = (long)g * 2048 + (long)hb * 64 + tau;
    if (p0 < outlen) {   // outlen, p0 multiples of 8 -> full tile in-bounds
        float o[8];
        #pragma unroll
        for (int i = 0; i < 8; ++i) {
            float lo, hi; upk2(acc2[i], lo, hi);
            o[i] = lo + hi;
        }
        float* op = out + (long)b * outlen + p0;
        reinterpret_cast<float4*>(op)[0] = make_float4(o[0], o[1], o[2], o[3]);
        reinterpret_cast<float4*>(op)[1] = make_float4(o[4], o[5], o[6], o[7]);
    }
}

extern "C" void kernel_launch(void* const* d_in, const int* in_sizes, int n_in,
                              void* d_out, int out_size)
{
    const float* d_filter = (const float*)d_in[0];   // [B, F, 65]
    const float* d_noise  = (const float*)d_in[1];   // [B, F, 64]
    float* d_o = (float*)d_out;                      // [B, (F-1)*64 + 192]

    const long nframes = (long)in_sizes[0] / 65;     // B*F
    const long B = ((long)out_size - 64 * nframes) / 128;
    const int  F = (int)(nframes / B);
    const long outlen = (long)(F - 1) * 64 + 192;
    const int  G = (int)((outlen + 2047) / 2048);

    dim3 grid((unsigned)G, (unsigned)B);
    filtered_noise_kernel<<<grid, THREADS>>>(d_filter, d_noise, d_o, F, outlen);
}